// round 11
// baseline (speedup 1.0000x reference)
#include <cuda_runtime.h>
#include <cuda_fp16.h>
#include <cstdint>
#include <cstddef>

// ============================================================================
// Problem constants
// ============================================================================
#define N_TOK 4096
#define DIM   1024

// ---- fp16 mma.sync m16n8k16 GEMM config ----
#define BM 128
#define BN 128
#define BKH 64                        // fp16 elems per K-stage (128 B/row)
#define LDH 72                        // padded smem row stride in halves (144 B)
#define TILE_H (128 * LDH)            // halves per tile (A or B)
#define BUF_H  (2 * TILE_H)           // A + B halves per stage
#define NSTAGE 3
#define SMEM_H (NSTAGE * BUF_H * 2)   // bytes = 110592

// ============================================================================
// Device scratch (fp16 planes; __device__ globals per allocation-free rule)
// ============================================================================
static __device__ __align__(256) __half g_tx  [N_TOK * DIM];
static __device__ __align__(256) __half g_im  [N_TOK * DIM];
static __device__ __align__(256) __half g_wt  [DIM * DIM];
static __device__ __align__(256) __half g_wi  [DIM * DIM];
static __device__ __align__(256) __half g_imT [DIM * N_TOK];
static __device__ __align__(256) __half g_txT [DIM * N_TOK];
static __device__ __align__(256) __half g_t   [N_TOK * DIM];
static __device__ __align__(256) __half g_i   [N_TOK * DIM];
static __device__ __align__(256) __half g_P   [(size_t)N_TOK * N_TOK];
static __device__ __align__(256) __half g_PT  [(size_t)N_TOK * N_TOK];
static __device__ __align__(256) float  g_rowsum[N_TOK];
static __device__ __align__(256) float  g_colsum[N_TOK];

// ============================================================================
// Helpers
// ============================================================================
__device__ __forceinline__ void cp_async16(void* dst_smem, const void* src) {
    uint32_t dst;
    asm("{ .reg .u64 t; cvta.to.shared.u64 t, %1; cvt.u32.u64 %0, t; }" : "=r"(dst) : "l"(dst_smem));
    asm volatile("cp.async.cg.shared.global [%0], [%1], 16;" :: "r"(dst), "l"(src) : "memory");
}
#define CP_COMMIT() asm volatile("cp.async.commit_group;" ::: "memory")
#define CP_WAIT(n)  asm volatile("cp.async.wait_group %0;" :: "n"(n) : "memory")

__device__ __forceinline__ uint32_t smem_addr32(const void* p) {
    uint32_t a;
    asm("{ .reg .u64 t; cvta.to.shared.u64 t, %1; cvt.u32.u64 %0, t; }" : "=r"(a) : "l"(p));
    return a;
}

__device__ __forceinline__ void ldsm_x4(uint32_t& r0, uint32_t& r1, uint32_t& r2, uint32_t& r3,
                                        uint32_t addr) {
    asm volatile("ldmatrix.sync.aligned.m8n8.x4.shared.b16 {%0,%1,%2,%3}, [%4];"
                 : "=r"(r0), "=r"(r1), "=r"(r2), "=r"(r3) : "r"(addr));
}

__device__ __forceinline__ void mma_f16(float& d0, float& d1, float& d2, float& d3,
                                        uint32_t a0, uint32_t a1, uint32_t a2, uint32_t a3,
                                        uint32_t b0, uint32_t b1) {
    asm volatile(
        "mma.sync.aligned.m16n8k16.row.col.f32.f16.f16.f32 "
        "{%0,%1,%2,%3}, {%4,%5,%6,%7}, {%8,%9}, {%0,%1,%2,%3};"
        : "+f"(d0), "+f"(d1), "+f"(d2), "+f"(d3)
        : "r"(a0), "r"(a1), "r"(a2), "r"(a3), "r"(b0), "r"(b1));
}

// ============================================================================
// fp16 GEMM:  D[m,n] = sum_k A[m,k] * B[n,k]   (NT, both K-major, fp32 accum)
// 3-stage cp.async pipeline, ONE __syncthreads per K-chunk,
// register-level fragment double-buffering (ks+1 loads overlap ks MMAs).
// blockIdx.z in {0,1} selects pointer set (merged independent GEMMs).
// MODE 0: C[m,n] = h(D + bias[n])                           (projections, fp16 out)
// MODE 1: e = h(exp(D/32)); C[m,n]=e; C2[n,m]=e             (logits -> P, P^T, fp16)
// MODE 2: Cf[m,n] = D * scale[0] / denom[m]                 (attn @ V, fp32 out)
// ============================================================================
template <int MODE>
__global__ __launch_bounds__(256, 2)
void gemm_h(const __half* __restrict__ A0, const __half* __restrict__ B0,
            const __half* __restrict__ A1, const __half* __restrict__ B1,
            int K, int ldA, int ldB,
            __half* __restrict__ C0h, __half* __restrict__ C1h, int ldC,
            __half* __restrict__ C2, int ldC2,
            float* __restrict__ Cf0, float* __restrict__ Cf1,
            const float* __restrict__ bias0, const float* __restrict__ bias1,
            const float* __restrict__ denom0, const float* __restrict__ denom1,
            const float* __restrict__ scale0p, const float* __restrict__ scale1p)
{
    extern __shared__ __half smemh[];
    const int z   = blockIdx.z;
    const __half* __restrict__ A = z ? A1 : A0;
    const __half* __restrict__ B = z ? B1 : B0;
    __half* __restrict__ C       = z ? C1h : C0h;
    float*  __restrict__ Cf      = z ? Cf1 : Cf0;
    const float* __restrict__ bias  = z ? bias1  : bias0;
    const float* __restrict__ denom = z ? denom1 : denom0;
    const float* __restrict__ scale = z ? scale1p : scale0p;

    const int tid = threadIdx.x;
    const int wid = tid >> 5;
    const int lid = tid & 31;
    const int mw  = wid >> 2;       // 0..1 -> 64 rows
    const int nw  = wid & 3;        // 0..3 -> 32 cols
    const int m0  = blockIdx.y * BM;
    const int n0  = blockIdx.x * BN;

    const __half* __restrict__ Ab = A + (size_t)m0 * ldA;
    const __half* __restrict__ Bb = B + (size_t)n0 * ldB;

    const uint32_t sbase = smem_addr32(smemh);

    float acc[4][4][4];
    #pragma unroll
    for (int i = 0; i < 4; i++)
        #pragma unroll
        for (int j = 0; j < 4; j++)
            #pragma unroll
            for (int c = 0; c < 4; c++) acc[i][j][c] = 0.0f;

    const int NK = K / BKH;

    auto fill = [&](int kt) {
        const int bufI = kt % NSTAGE;
        const int kofs = kt * BKH;
        char* base = (char*)smemh + bufI * BUF_H * 2;
        #pragma unroll
        for (int i = 0; i < 8; i++) {
            const int idx = tid + i * 256;        // 0..2047 16B-chunks
            const int isB = idx >> 10;
            const int cc  = idx & 1023;
            const int row = cc >> 3;              // 0..127
            const int ch  = cc & 7;               // 16B chunk (8 halves)
            const __half* src = (isB ? (Bb + (size_t)row * ldB) : (Ab + (size_t)row * ldA))
                                + kofs + ch * 8;
            char* dst = base + (isB ? TILE_H * 2 : 0) + row * (LDH * 2) + ch * 16;
            cp_async16(dst, src);
        }
        CP_COMMIT();
    };

    // Prologue: fill NSTAGE-1 = 2 stages.
    fill(0);
    if (NK > 1) fill(1);

    // per-lane ldmatrix address offsets (bytes)
    const uint32_t a_lane = (uint32_t)(((lid & 15) * LDH + (lid >> 4) * 8) * 2);
    const uint32_t b_lane = (uint32_t)((((lid & 7) + ((lid >> 4) << 3)) * LDH
                                        + ((lid >> 3) & 1) * 8) * 2);

    // double-buffered fragments: [parity][...]
    uint32_t af[2][4][4];
    uint32_t bf[2][4][2];

    for (int kt = 0; kt < NK; kt++) {
        const int b = kt % NSTAGE;
        // pending groups before wait: fill(kt) and (if issued) fill(kt+1)
        if (kt + 1 < NK) { CP_WAIT(1); } else { CP_WAIT(0); }
        __syncthreads();    // fill(kt) visible; all warps done reading stage (kt+2)%3

        const uint32_t Abase = sbase + (uint32_t)(b * BUF_H * 2) + (uint32_t)(mw * 64 * LDH * 2)
                             + a_lane;
        const uint32_t Bbase = sbase + (uint32_t)(b * BUF_H * 2) + (uint32_t)(TILE_H * 2)
                             + (uint32_t)(nw * 32 * LDH * 2) + b_lane;

        // ks=0 fragment loads FIRST (critical path), then async fill issue.
        #pragma unroll
        for (int i = 0; i < 4; i++)
            ldsm_x4(af[0][i][0], af[0][i][1], af[0][i][2], af[0][i][3],
                    Abase + (uint32_t)(i * 16 * LDH * 2));
        #pragma unroll
        for (int jj = 0; jj < 2; jj++)
            ldsm_x4(bf[0][jj * 2][0], bf[0][jj * 2][1], bf[0][jj * 2 + 1][0], bf[0][jj * 2 + 1][1],
                    Bbase + (uint32_t)(jj * 16 * LDH * 2));

        // Write stage (kt+2)%3 — the stage read at iter kt-1; safe after the barrier.
        if (kt + 2 < NK) fill(kt + 2);

        #pragma unroll
        for (int ks = 0; ks < 4; ks++) {
            const int cur = ks & 1;
            if (ks < 3) {
                const int nxt = (ks + 1) & 1;
                const uint32_t kb = (uint32_t)((ks + 1) * 16 * 2);
                #pragma unroll
                for (int i = 0; i < 4; i++)
                    ldsm_x4(af[nxt][i][0], af[nxt][i][1], af[nxt][i][2], af[nxt][i][3],
                            Abase + (uint32_t)(i * 16 * LDH * 2) + kb);
                #pragma unroll
                for (int jj = 0; jj < 2; jj++)
                    ldsm_x4(bf[nxt][jj * 2][0], bf[nxt][jj * 2][1],
                            bf[nxt][jj * 2 + 1][0], bf[nxt][jj * 2 + 1][1],
                            Bbase + (uint32_t)(jj * 16 * LDH * 2) + kb);
            }
            #pragma unroll
            for (int i = 0; i < 4; i++)
                #pragma unroll
                for (int j = 0; j < 4; j++)
                    mma_f16(acc[i][j][0], acc[i][j][1], acc[i][j][2], acc[i][j][3],
                            af[cur][i][0], af[cur][i][1], af[cur][i][2], af[cur][i][3],
                            bf[cur][j][0], bf[cur][j][1]);
        }
        // no second barrier: stage b is not refilled until iter kt+1's barrier has
        // confirmed every warp left it (write stage trails read stage by 2).
    }

    // ---------------- Epilogue ----------------
    const int g = lid >> 2;
    const int q = lid & 3;
    const float sc_glob = (MODE == 2) ? scale[0] : 0.0f;
    __half* bufT = smemh;     // MODE 1 transpose staging: [128 n][132 m] halves
    if (MODE == 1) __syncthreads();   // all warps done with mainloop smem before reuse

    #pragma unroll
    for (int i = 0; i < 4; i++) {
        const int r0 = mw * 64 + i * 16 + g;
        const int r1 = r0 + 8;
        float sc0 = 1.0f, sc1 = 1.0f;
        if (MODE == 2) {
            sc0 = sc_glob / __ldg(&denom[m0 + r0]);
            sc1 = sc_glob / __ldg(&denom[m0 + r1]);
        }
        #pragma unroll
        for (int j = 0; j < 4; j++) {
            const int c0 = nw * 32 + j * 8 + 2 * q;
            float v00 = acc[i][j][0], v01 = acc[i][j][1];
            float v10 = acc[i][j][2], v11 = acc[i][j][3];
            if (MODE == 0) {
                const float b0 = __ldg(&bias[n0 + c0]);
                const float b1 = __ldg(&bias[n0 + c0 + 1]);
                __half2 h0 = __floats2half2_rn(v00 + b0, v01 + b1);
                __half2 h1 = __floats2half2_rn(v10 + b0, v11 + b1);
                *(__half2*)(C + (size_t)(m0 + r0) * ldC + n0 + c0) = h0;
                *(__half2*)(C + (size_t)(m0 + r1) * ldC + n0 + c0) = h1;
            } else if (MODE == 1) {
                __half2 h0 = __floats2half2_rn(__expf(v00 * 0.03125f), __expf(v01 * 0.03125f));
                __half2 h1 = __floats2half2_rn(__expf(v10 * 0.03125f), __expf(v11 * 0.03125f));
                *(__half2*)(C + (size_t)(m0 + r0) * ldC + n0 + c0) = h0;
                *(__half2*)(C + (size_t)(m0 + r1) * ldC + n0 + c0) = h1;
                bufT[(c0    ) * 132 + r0] = __low2half(h0);
                bufT[(c0 + 1) * 132 + r0] = __high2half(h0);
                bufT[(c0    ) * 132 + r1] = __low2half(h1);
                bufT[(c0 + 1) * 132 + r1] = __high2half(h1);
            } else {
                float2 f0 = make_float2(v00 * sc0, v01 * sc0);
                float2 f1 = make_float2(v10 * sc1, v11 * sc1);
                *(float2*)(Cf + (size_t)(m0 + r0) * ldC + n0 + c0) = f0;
                *(float2*)(Cf + (size_t)(m0 + r1) * ldC + n0 + c0) = f1;
            }
        }
    }

    if (MODE == 1) {
        __syncthreads();
        for (int r = wid * 16; r < wid * 16 + 16; r++) {
            uint32_t* dst32 = (uint32_t*)(C2 + (size_t)(n0 + r) * ldC2 + m0);
            const uint32_t* src32 = (const uint32_t*)(bufT + r * 132);
            dst32[lid]      = src32[lid];
            dst32[lid + 32] = src32[lid + 32];
        }
    }
}

// ============================================================================
// Helper kernels
// ============================================================================
// Fused: fp32 -> fp16 plane AND fp16 transposed plane; z selects text/image.
__global__ void convtrans2_k(const float* __restrict__ in0, __half* __restrict__ out0,
                             __half* __restrict__ out0T,
                             const float* __restrict__ in1, __half* __restrict__ out1,
                             __half* __restrict__ out1T, int rows, int cols) {
    __shared__ float t[32][33];
    const float* in = blockIdx.z ? in1 : in0;
    __half* out     = blockIdx.z ? out1 : out0;
    __half* outT    = blockIdx.z ? out1T : out0T;
    const int x0 = blockIdx.x * 32, y0 = blockIdx.y * 32;
    for (int j = threadIdx.y; j < 32; j += 8) {
        float v = in[(size_t)(y0 + j) * cols + x0 + threadIdx.x];
        t[j][threadIdx.x] = v;
        out[(size_t)(y0 + j) * cols + x0 + threadIdx.x] = __float2half_rn(v);
    }
    __syncthreads();
    for (int j = threadIdx.y; j < 32; j += 8)
        outT[(size_t)(x0 + j) * rows + y0 + threadIdx.x] = __float2half_rn(t[threadIdx.x][j]);
}

// Merged fp32->fp16 for both weight matrices (blockIdx.y selects).
__global__ void tohalf2_k(const float4* __restrict__ in0, __half2* __restrict__ out0,
                          const float4* __restrict__ in1, __half2* __restrict__ out1, int n4) {
    int i = blockIdx.x * blockDim.x + threadIdx.x;
    const float4* in = blockIdx.y ? in1 : in0;
    __half2* out     = blockIdx.y ? out1 : out0;
    if (i < n4) {
        float4 a = in[i];
        out[2 * i]     = __floats2half2_rn(a.x, a.y);
        out[2 * i + 1] = __floats2half2_rn(a.z, a.w);
    }
}

// Merged rowsum over P (y=0 -> rs) and PT (y=1 -> cs).
__global__ void rowsum_h2_k(const __half2* __restrict__ P0, float* __restrict__ out0,
                            const __half2* __restrict__ P1, float* __restrict__ out1,
                            int ncols) {
    __shared__ float red[256];
    const __half2* P2 = blockIdx.y ? P1 : P0;
    float* out        = blockIdx.y ? out1 : out0;
    const __half2* row = P2 + (size_t)blockIdx.x * (ncols / 2);
    float s = 0.0f;
    for (int j = threadIdx.x; j < ncols / 2; j += 256) {
        float2 v = __half22float2(row[j]);
        s += v.x + v.y;
    }
    red[threadIdx.x] = s;
    __syncthreads();
    for (int o = 128; o > 0; o >>= 1) {
        if (threadIdx.x < o) red[threadIdx.x] += red[threadIdx.x + o];
        __syncthreads();
    }
    if (threadIdx.x == 0) out[blockIdx.x] = red[0];
}

// ============================================================================
// Host launch
// ============================================================================
extern "C" void kernel_launch(void* const* d_in, const int* in_sizes, int n_in,
                              void* d_out, int out_size) {
    const float* text    = (const float*)d_in[0];
    const float* image   = (const float*)d_in[1];
    const float* w_text  = (const float*)d_in[2];
    const float* b_text  = (const float*)d_in[3];
    const float* w_image = (const float*)d_in[4];
    const float* b_image = (const float*)d_in[5];
    const float* s_TI    = (const float*)d_in[6];
    const float* s_IT    = (const float*)d_in[7];
    float* out = (float*)d_out;

    __half *tx, *im, *wt, *wi, *imT, *txT, *th, *ih, *P, *PT;
    float *rs, *cs;
    cudaGetSymbolAddress((void**)&tx,  g_tx);
    cudaGetSymbolAddress((void**)&im,  g_im);
    cudaGetSymbolAddress((void**)&wt,  g_wt);
    cudaGetSymbolAddress((void**)&wi,  g_wi);
    cudaGetSymbolAddress((void**)&imT, g_imT);
    cudaGetSymbolAddress((void**)&txT, g_txT);
    cudaGetSymbolAddress((void**)&th,  g_t);
    cudaGetSymbolAddress((void**)&ih,  g_i);
    cudaGetSymbolAddress((void**)&P,   g_P);
    cudaGetSymbolAddress((void**)&PT,  g_PT);
    cudaGetSymbolAddress((void**)&rs,  g_rowsum);
    cudaGetSymbolAddress((void**)&cs,  g_colsum);

    cudaFuncSetAttribute((const void*)gemm_h<0>, cudaFuncAttributeMaxDynamicSharedMemorySize, SMEM_H);
    cudaFuncSetAttribute((const void*)gemm_h<1>, cudaFuncAttributeMaxDynamicSharedMemorySize, SMEM_H);
    cudaFuncSetAttribute((const void*)gemm_h<2>, cudaFuncAttributeMaxDynamicSharedMemorySize, SMEM_H);

    // 1) fused fp16 conversion + transpose for text / image (single launch)
    {
        dim3 blk(32, 8);
        dim3 grd(DIM / 32, N_TOK / 32, 2);
        convtrans2_k<<<grd, blk>>>(text, tx, txT, image, im, imT, N_TOK, DIM);
    }
    // 2) weights -> fp16 (merged)
    {
        int w4 = DIM * DIM / 4;
        dim3 grd((w4 + 255) / 256, 2);
        tohalf2_k<<<grd, 256>>>((const float4*)w_text,  (__half2*)wt,
                                (const float4*)w_image, (__half2*)wi, w4);
    }
    // 3) projections merged:  t = text@wt^T+b_t (z=0),  i = image@wi^T+b_i (z=1)
    {
        dim3 grd(DIM / BN, N_TOK / BM, 2);
        gemm_h<0><<<grd, 256, SMEM_H>>>(tx, wt, im, wi, DIM, DIM, DIM,
                                        th, ih, DIM, nullptr, 0,
                                        nullptr, nullptr,
                                        b_text, b_image, nullptr, nullptr, nullptr, nullptr);
    }
    // 4) logits + exp:  P = exp((t @ i^T)/32),  PT = P^T
    {
        dim3 grd(N_TOK / BN, N_TOK / BM, 1);
        gemm_h<1><<<grd, 256, SMEM_H>>>(th, ih, th, ih, DIM, DIM, DIM,
                                        P, P, N_TOK, PT, N_TOK,
                                        nullptr, nullptr,
                                        nullptr, nullptr, nullptr, nullptr, nullptr, nullptr);
    }
    // 5) softmax denominators (merged)
    {
        dim3 grd(N_TOK, 2);
        rowsum_h2_k<<<grd, 256>>>((const __half2*)P, rs, (const __half2*)PT, cs, N_TOK);
    }
    // 6) outputs merged: out1 = (P@image)*s_TI/rs (z=0), out2 = (PT@text)*s_IT/cs (z=1)
    {
        dim3 grd(DIM / BN, N_TOK / BM, 2);
        gemm_h<2><<<grd, 256, SMEM_H>>>(P, imT, PT, txT, N_TOK, N_TOK, N_TOK,
                                        nullptr, nullptr, DIM, nullptr, 0,
                                        out, out + (size_t)N_TOK * DIM,
                                        nullptr, nullptr, rs, cs, s_TI, s_IT);
    }
}